// round 2
// baseline (speedup 1.0000x reference)
#include <cuda_runtime.h>
#include <math.h>

#define BB 16
#define TT 800
#define LL 160
#define DD 80
#define KK2 (2*DD)          // GEMM K dimension = 160
#define NEG_INFF (-1e20f)
#define HALF_LOG2PI 0.9189385332046727f   // 0.5*log(2*pi)

// Scratch: W [b][k][l], k in [0,160): first 80 = -0.5*inv_var, next 80 = mu*inv_var.
// C[b][l] = -0.5*q_mu - 0.5*sum(log_sigma) - 0.5*D*log(2pi)
__device__ float g_W[BB * KK2 * LL];
__device__ float g_C[BB * LL];

// ---------------------------------------------------------------------------
// K0: per-(b,l) parameter transform. One warp per (b,l); 2560 warps total.
// Also zeroes the loss scalar (d_out is poisoned by the harness).
// ---------------------------------------------------------------------------
__global__ void param_kernel(const float* __restrict__ mu_sigma,
                             float* __restrict__ loss) {
    if (blockIdx.x == 0 && threadIdx.x == 0) *loss = 0.f;

    int wl   = (blockIdx.x * blockDim.x + threadIdx.x) >> 5;
    int lane = threadIdx.x & 31;
    if (wl >= BB * LL) return;
    int b = wl / LL, l = wl % LL;
    const float* ms = mu_sigma + (size_t)(b * LL + l) * KK2;

    float qmu = 0.f, sl = 0.f;
    for (int d = lane; d < DD; d += 32) {
        float mu = 4.f / (1.f + __expf(-ms[d]));        // sigmoid(x)*4
        float ls = 4.f * tanhf(ms[DD + d]);             // tanh(x)*4
        float iv = __expf(-2.f * ls);                   // exp(-2*log_sigma)
        g_W[((size_t)b * KK2 + d)      * LL + l] = -0.5f * iv;
        g_W[((size_t)b * KK2 + DD + d) * LL + l] = mu * iv;
        qmu += mu * mu * iv;
        sl  += ls;
    }
#pragma unroll
    for (int o = 16; o; o >>= 1) {
        qmu += __shfl_xor_sync(0xffffffffu, qmu, o);
        sl  += __shfl_xor_sync(0xffffffffu, sl, o);
    }
    if (lane == 0)
        g_C[b * LL + l] = -0.5f * qmu - 0.5f * sl - (float)DD * HALF_LOG2PI;
}

// ---------------------------------------------------------------------------
// K1: log_prob as batched SGEMM: lp[b,t,l] = sum_k X[t,k]*W[k,l] + C[l]
// X[t,k] = mel[t,k]^2 (k<80) or mel[t,k-80] (k>=80), built on the fly.
// 64x64 tile, 256 threads, 4x4 per thread, BK=16 (K=160 -> 10 iters exact).
// ---------------------------------------------------------------------------
#define BK 16
__global__ void __launch_bounds__(256) lp_gemm(const float* __restrict__ mel,
                                               float* __restrict__ lp_out) {
    __shared__ float As[64][BK + 1];
    __shared__ float Bs[BK][64];

    int b  = blockIdx.z;
    int m0 = blockIdx.x * 64;
    int n0 = blockIdx.y * 64;
    int tid = threadIdx.x;
    int tx = tid & 15, ty = tid >> 4;

    const float* melb = mel + (size_t)b * TT * DD;
    const float* Wb   = g_W + (size_t)b * KK2 * LL;

    float acc[4][4];
#pragma unroll
    for (int i = 0; i < 4; i++)
#pragma unroll
        for (int j = 0; j < 4; j++) acc[i][j] = 0.f;

    for (int k0 = 0; k0 < KK2; k0 += BK) {
        bool sq = (k0 < DD);
        int  kc = sq ? k0 : (k0 - DD);   // mel column base; tile never straddles 80
#pragma unroll
        for (int i = 0; i < 4; i++) {
            int lin = tid + i * 256;
            int mm = lin >> 4, kk = lin & 15;
            int t = m0 + mm; if (t > TT - 1) t = TT - 1;   // clamp (guard at store)
            float v = melb[(size_t)t * DD + kc + kk];
            As[mm][kk] = sq ? v * v : v;
        }
#pragma unroll
        for (int i = 0; i < 4; i++) {
            int lin = tid + i * 256;
            int kk = lin >> 6, nn = lin & 63;
            int l = n0 + nn;
            Bs[kk][nn] = (l < LL) ? Wb[(size_t)(k0 + kk) * LL + l] : 0.f;
        }
        __syncthreads();
#pragma unroll
        for (int kk = 0; kk < BK; kk++) {
            float a0 = As[ty * 4 + 0][kk];
            float a1 = As[ty * 4 + 1][kk];
            float a2 = As[ty * 4 + 2][kk];
            float a3 = As[ty * 4 + 3][kk];
            float4 bv = *(const float4*)&Bs[kk][tx * 4];
            acc[0][0] += a0 * bv.x; acc[0][1] += a0 * bv.y; acc[0][2] += a0 * bv.z; acc[0][3] += a0 * bv.w;
            acc[1][0] += a1 * bv.x; acc[1][1] += a1 * bv.y; acc[1][2] += a1 * bv.z; acc[1][3] += a1 * bv.w;
            acc[2][0] += a2 * bv.x; acc[2][1] += a2 * bv.y; acc[2][2] += a2 * bv.z; acc[2][3] += a2 * bv.w;
            acc[3][0] += a3 * bv.x; acc[3][1] += a3 * bv.y; acc[3][2] += a3 * bv.z; acc[3][3] += a3 * bv.w;
        }
        __syncthreads();
    }

#pragma unroll
    for (int i = 0; i < 4; i++) {
        int t = m0 + ty * 4 + i;
        if (t >= TT) continue;
#pragma unroll
        for (int j = 0; j < 4; j++) {
            int l = n0 + tx * 4 + j;
            if (l < LL)
                lp_out[((size_t)b * TT + t) * LL + l] = acc[i][j] + g_C[b * LL + l];
        }
    }
}

// ---------------------------------------------------------------------------
// K2: sequential alpha scan, barrier-free. One block per batch, 160 threads.
// Warp w owns l in [32w, 32w+32). Cross-warp dependency (alpha[32w-1] at t-1)
// goes through a 64-bit volatile shared mailbox bound[w][t] = (tag=t+1, bits).
// Single aligned STS.64 / LDS.64 => value+tag atomic, no fence needed.
// Producers never block (full history), consumers spin (steady state: 1 poll).
// Loss is fused: -mean(alpha[b, ml-1, cl-1]) accumulated via atomicAdd.
// ---------------------------------------------------------------------------
__global__ void __launch_bounds__(LL) scan_kernel(const float* __restrict__ lp,
                                                  float* __restrict__ alphas,
                                                  const int* __restrict__ ml,
                                                  const int* __restrict__ cl,
                                                  float* __restrict__ loss) {
    __shared__ volatile unsigned long long bound[4][TT];   // 25.6 KB

    int b    = blockIdx.x;
    int l    = threadIdx.x;
    int w    = l >> 5, lane = l & 31;

    // zero tags once
    for (int i = l; i < 4 * TT; i += LL)
        ((volatile unsigned long long*)bound)[i] = 0ull;

    const float* lpb = lp + (size_t)b * TT * LL;
    float* ab = alphas + (size_t)b * TT * LL;
    int mlb = ml[b] - 1;        // in [T/2-1, T-1]
    int clb = cl[b] - 1;

    __syncthreads();            // tags visible before any producer writes

    float alpha = (l == 0) ? lpb[0] : NEG_INFF;
    ab[l] = alpha;
    if (lane == 31 && w < 4)
        bound[w][0] = (1ull << 32) | (unsigned long long)__float_as_uint(alpha);

    // depth-2 prefetch of lp rows
    float lpn0 = lpb[(size_t)1 * LL + l];
    float lpn1 = lpb[(size_t)2 * LL + l];

    for (int t = 1; t < TT; t++) {
        float lpv = lpn0;
        lpn0 = lpn1;
        lpn1 = (t + 2 < TT) ? lpb[(size_t)(t + 2) * LL + l] : 0.f;

        float up = __shfl_up_sync(0xffffffffu, alpha, 1);
        float prev;
        if (lane == 0) {
            if (w == 0) {
                prev = NEG_INFF;
            } else {
                unsigned long long v;
                do { v = bound[w - 1][t - 1]; } while ((unsigned)(v >> 32) != (unsigned)t);
                prev = __uint_as_float((unsigned)v);
            }
        } else {
            prev = up;
        }

        float m = fmaxf(alpha, prev);
        float d = fminf(alpha, prev) - m;                  // <= 0
        alpha = m + __logf(1.f + __expf(d)) + lpv;

        if (lane == 31 && w < 4)
            bound[w][t] = ((unsigned long long)(unsigned)(t + 1) << 32)
                        | (unsigned long long)__float_as_uint(alpha);
        ab[(size_t)t * LL + l] = alpha;

        if (t == mlb && l == clb)
            atomicAdd(loss, -alpha * (1.0f / (float)BB));
    }
}

// ---------------------------------------------------------------------------
extern "C" void kernel_launch(void* const* d_in, const int* in_sizes, int n_in,
                              void* d_out, int out_size) {
    const float* mel      = (const float*)d_in[0];
    const float* mu_sigma = (const float*)d_in[1];
    const int*   ml       = (const int*)d_in[2];
    const int*   cl       = (const int*)d_in[3];

    float* out    = (float*)d_out;
    float* lp     = out;                              // [B,T,L]
    float* loss   = out + (size_t)BB * TT * LL;       // [1]
    float* alphas = loss + 1;                         // [B,T,L]

    param_kernel<<<(BB * LL * 32 + 127) / 128, 128>>>(mu_sigma, loss);

    dim3 g((TT + 63) / 64, (LL + 63) / 64, BB);       // 13 x 3 x 16
    lp_gemm<<<g, 256>>>(mel, lp);

    scan_kernel<<<BB, LL>>>(lp, alphas, ml, cl, loss);
}

// round 3
// speedup vs baseline: 1.0586x; 1.0586x over previous
#include <cuda_runtime.h>
#include <math.h>

#define BB 16
#define TT 800
#define LL 160
#define DD 80
#define KK2 (2*DD)          // GEMM K dimension = 160
#define NEG_INFF (-1e20f)
#define HALF_LOG2PI 0.9189385332046727f   // 0.5*log(2*pi)
#define LOG2E_F 1.4426950408889634f
#define LN2_F   0.6931471805599453f
// -1e20 in log2 units: scales back to ~-1e20 on output (rel err ~1e-7)
#define NEG_INF2 (-1.4426950408889634e20f)

// Scratch: W [b][k][l], k in [0,160): first 80 = -0.5*inv_var, next 80 = mu*inv_var.
// C[b][l] = -0.5*q_mu - 0.5*sum(log_sigma) - 0.5*D*log(2pi)
__device__ float g_W[BB * KK2 * LL];
__device__ float g_C[BB * LL];

// ---------------------------------------------------------------------------
// K0: per-(b,l) parameter transform. One warp per (b,l). Also zeroes the loss.
// ---------------------------------------------------------------------------
__global__ void param_kernel(const float* __restrict__ mu_sigma,
                             float* __restrict__ loss) {
    if (blockIdx.x == 0 && threadIdx.x == 0) *loss = 0.f;

    int wl   = (blockIdx.x * blockDim.x + threadIdx.x) >> 5;
    int lane = threadIdx.x & 31;
    if (wl >= BB * LL) return;
    int b = wl / LL, l = wl % LL;
    const float* ms = mu_sigma + (size_t)(b * LL + l) * KK2;

    float qmu = 0.f, sl = 0.f;
    for (int d = lane; d < DD; d += 32) {
        float mu = 4.f / (1.f + __expf(-ms[d]));        // sigmoid(x)*4
        float ls = 4.f * tanhf(ms[DD + d]);             // tanh(x)*4
        float iv = __expf(-2.f * ls);                   // exp(-2*log_sigma)
        g_W[((size_t)b * KK2 + d)      * LL + l] = -0.5f * iv;
        g_W[((size_t)b * KK2 + DD + d) * LL + l] = mu * iv;
        qmu += mu * mu * iv;
        sl  += ls;
    }
#pragma unroll
    for (int o = 16; o; o >>= 1) {
        qmu += __shfl_xor_sync(0xffffffffu, qmu, o);
        sl  += __shfl_xor_sync(0xffffffffu, sl, o);
    }
    if (lane == 0)
        g_C[b * LL + l] = -0.5f * qmu - 0.5f * sl - (float)DD * HALF_LOG2PI;
}

// ---------------------------------------------------------------------------
// K1: log_prob as batched SGEMM: lp[b,t,l] = sum_k X[t,k]*W[k,l] + C[l]
// ---------------------------------------------------------------------------
#define BK 16
__global__ void __launch_bounds__(256) lp_gemm(const float* __restrict__ mel,
                                               float* __restrict__ lp_out) {
    __shared__ float As[64][BK + 1];
    __shared__ float Bs[BK][64];

    int b  = blockIdx.z;
    int m0 = blockIdx.x * 64;
    int n0 = blockIdx.y * 64;
    int tid = threadIdx.x;
    int tx = tid & 15, ty = tid >> 4;

    const float* melb = mel + (size_t)b * TT * DD;
    const float* Wb   = g_W + (size_t)b * KK2 * LL;

    float acc[4][4];
#pragma unroll
    for (int i = 0; i < 4; i++)
#pragma unroll
        for (int j = 0; j < 4; j++) acc[i][j] = 0.f;

    for (int k0 = 0; k0 < KK2; k0 += BK) {
        bool sq = (k0 < DD);
        int  kc = sq ? k0 : (k0 - DD);   // mel column base; tile never straddles 80
#pragma unroll
        for (int i = 0; i < 4; i++) {
            int lin = tid + i * 256;
            int mm = lin >> 4, kk = lin & 15;
            int t = m0 + mm; if (t > TT - 1) t = TT - 1;   // clamp (guard at store)
            float v = melb[(size_t)t * DD + kc + kk];
            As[mm][kk] = sq ? v * v : v;
        }
#pragma unroll
        for (int i = 0; i < 4; i++) {
            int lin = tid + i * 256;
            int kk = lin >> 6, nn = lin & 63;
            int l = n0 + nn;
            Bs[kk][nn] = (l < LL) ? Wb[(size_t)(k0 + kk) * LL + l] : 0.f;
        }
        __syncthreads();
#pragma unroll
        for (int kk = 0; kk < BK; kk++) {
            float a0 = As[ty * 4 + 0][kk];
            float a1 = As[ty * 4 + 1][kk];
            float a2 = As[ty * 4 + 2][kk];
            float a3 = As[ty * 4 + 3][kk];
            float4 bv = *(const float4*)&Bs[kk][tx * 4];
            acc[0][0] += a0 * bv.x; acc[0][1] += a0 * bv.y; acc[0][2] += a0 * bv.z; acc[0][3] += a0 * bv.w;
            acc[1][0] += a1 * bv.x; acc[1][1] += a1 * bv.y; acc[1][2] += a1 * bv.z; acc[1][3] += a1 * bv.w;
            acc[2][0] += a2 * bv.x; acc[2][1] += a2 * bv.y; acc[2][2] += a2 * bv.z; acc[2][3] += a2 * bv.w;
            acc[3][0] += a3 * bv.x; acc[3][1] += a3 * bv.y; acc[3][2] += a3 * bv.z; acc[3][3] += a3 * bv.w;
        }
        __syncthreads();
    }

#pragma unroll
    for (int i = 0; i < 4; i++) {
        int t = m0 + ty * 4 + i;
        if (t >= TT) continue;
#pragma unroll
        for (int j = 0; j < 4; j++) {
            int l = n0 + tx * 4 + j;
            if (l < LL)
                lp_out[((size_t)b * TT + t) * LL + l] = acc[i][j] + g_C[b * LL + l];
        }
    }
}

// ---------------------------------------------------------------------------
// K2: barrier-free scan with uniform (non-divergent) mailbox polling.
// One block per batch, 160 threads = 5 warps, one l per thread.
// bound[row][t]: row 0 = pre-filled dummy (for warp 0); warp w reads row w,
// writes row w+1 (w<4). 64-bit word = (tag = t+1) << 32 | alpha2 bits.
// All lanes poll the same word (broadcast LDS); poll for step t+1 is issued
// at the TOP of step t so its latency hides under the logaddexp chain.
// ---------------------------------------------------------------------------
__device__ __forceinline__ unsigned long long lds64v(unsigned a) {
    unsigned long long v;
    asm volatile("ld.volatile.shared.u64 %0, [%1];" : "=l"(v) : "r"(a));
    return v;
}
__device__ __forceinline__ void sts64v(unsigned a, unsigned long long v) {
    asm volatile("st.volatile.shared.u64 [%0], %1;" :: "r"(a), "l"(v));
}
__device__ __forceinline__ float ex2f_(float x) {
    float r; asm("ex2.approx.ftz.f32 %0, %1;" : "=f"(r) : "f"(x)); return r;
}
__device__ __forceinline__ float lg2f_(float x) {
    float r; asm("lg2.approx.ftz.f32 %0, %1;" : "=f"(r) : "f"(x)); return r;
}

__global__ void __launch_bounds__(LL) scan_kernel(const float* __restrict__ lp,
                                                  float* __restrict__ alphas,
                                                  const int* __restrict__ ml,
                                                  const int* __restrict__ cl,
                                                  float* __restrict__ loss) {
    __shared__ unsigned long long bound[5][TT];   // 32 KB

    int b = blockIdx.x;
    int l = threadIdx.x;
    int w = l >> 5, lane = l & 31;

    // init mailboxes: row 0 = dummy (tag s+1, value NEG_INF2); rows 1..4 tag 0
    {
        unsigned long long dummy_lo = (unsigned long long)__float_as_uint(NEG_INF2);
        for (int i = l; i < 5 * TT; i += LL) {
            int row = i / TT, s = i - row * TT;
            ((unsigned long long*)bound)[i] =
                (row == 0) ? (((unsigned long long)(unsigned)(s + 1) << 32) | dummy_lo)
                           : 0ull;
        }
    }

    const float* lpb = lp + (size_t)b * TT * LL;
    float* ab = alphas + (size_t)b * TT * LL;
    int mlb = ml[b] - 1;
    int clb = cl[b] - 1;

    unsigned mbr = (unsigned)__cvta_generic_to_shared(&bound[w][0]);   // read row
    unsigned mbw = mbr + (unsigned)(TT * 8);                            // write row (w+1)
    bool producer = (lane == 31) && (w < 4);

    __syncthreads();   // mailbox init visible before any write

    // t = 0
    float alpha2 = (l == 0) ? lpb[0] * LOG2E_F : NEG_INF2;
    ab[l] = alpha2 * LN2_F;
    if (producer)
        sts64v(mbw + 0, (1ull << 32) | (unsigned long long)__float_as_uint(alpha2));

    // depth-4 lp prefetch
    float lp0 = lpb[(size_t)1 * LL + l];
    float lp1 = lpb[(size_t)2 * LL + l];
    float lp2r = lpb[(size_t)3 * LL + l];
    float lp3 = lpb[(size_t)4 * LL + l];

    // validated mailbox value for step 1 (slot 0, tag 1)
    unsigned long long v = lds64v(mbr);
    while ((unsigned)(v >> 32) != 1u) v = lds64v(mbr);

    for (int t = 1; t < TT; t++) {
        // issue next-step mailbox load early (slot t, want tag t+1)
        unsigned mba = mbr + (unsigned)t * 8u;
        unsigned long long vnext = lds64v(mba);

        float lpv = lp0;
        lp0 = lp1; lp1 = lp2r; lp2r = lp3;
        lp3 = (t + 4 < TT) ? lpb[(size_t)(t + 4) * LL + l] : 0.f;

        float up   = __shfl_up_sync(0xffffffffu, alpha2, 1);
        float mbv  = __uint_as_float((unsigned)v);
        float prev = lane ? up : mbv;                      // SEL, no branch

        float m2 = fmaxf(alpha2, prev);
        float mn = fminf(alpha2, prev);
        float e  = ex2f_(mn - m2);                         // 2^d, d<=0
        float lg = lg2f_(1.f + e);
        float mlp = m2 + lpv * LOG2E_F;
        alpha2 = mlp + lg;

        if (producer)
            sts64v(mbw + (unsigned)t * 8u,
                   ((unsigned long long)(unsigned)(t + 1) << 32)
                   | (unsigned long long)__float_as_uint(alpha2));

        ab[(size_t)t * LL + l] = alpha2 * LN2_F;

        if (t == mlb && l == clb)
            atomicAdd(loss, -alpha2 * (LN2_F / (float)BB));

        // validate prefetched mailbox for next step (usually already good)
        unsigned exp_tag = (unsigned)(t + 1);
        while ((unsigned)(vnext >> 32) != exp_tag) vnext = lds64v(mba);
        v = vnext;
    }
}

// ---------------------------------------------------------------------------
extern "C" void kernel_launch(void* const* d_in, const int* in_sizes, int n_in,
                              void* d_out, int out_size) {
    const float* mel      = (const float*)d_in[0];
    const float* mu_sigma = (const float*)d_in[1];
    const int*   ml       = (const int*)d_in[2];
    const int*   cl       = (const int*)d_in[3];

    float* out    = (float*)d_out;
    float* lp     = out;                              // [B,T,L]
    float* loss   = out + (size_t)BB * TT * LL;       // [1]
    float* alphas = loss + 1;                         // [B,T,L]

    param_kernel<<<(BB * LL * 32 + 127) / 128, 128>>>(mu_sigma, loss);

    dim3 g((TT + 63) / 64, (LL + 63) / 64, BB);       // 13 x 3 x 16
    lp_gemm<<<g, 256>>>(mel, lp);

    scan_kernel<<<BB, LL>>>(lp, alphas, ml, cl, loss);
}

// round 4
// speedup vs baseline: 1.4750x; 1.3933x over previous
#include <cuda_runtime.h>
#include <math.h>

#define BB 16
#define TT 800
#define LL 160
#define DD 80
#define KK2 (2*DD)
#define HALF_LOG2PI 0.9189385332046727f
#define LOG2E_F 1.4426950408889634f
#define LN2_F   0.6931471805599453f
#define NEG_INF2 (-1.4426950408889634e20f)   // -1e20 in log2 units

__device__ float g_W[BB * KK2 * LL];
__device__ float g_C[BB * LL];

// ---------------------------------------------------------------------------
// K0: per-(b,l) parameter transform. One warp per (b,l). Also zeroes the loss.
// ---------------------------------------------------------------------------
__global__ void param_kernel(const float* __restrict__ mu_sigma,
                             float* __restrict__ loss) {
    if (blockIdx.x == 0 && threadIdx.x == 0) *loss = 0.f;

    int wl   = (blockIdx.x * blockDim.x + threadIdx.x) >> 5;
    int lane = threadIdx.x & 31;
    if (wl >= BB * LL) return;
    int b = wl / LL, l = wl % LL;
    const float* ms = mu_sigma + (size_t)(b * LL + l) * KK2;

    float qmu = 0.f, sl = 0.f;
    for (int d = lane; d < DD; d += 32) {
        float mu = 4.f / (1.f + __expf(-ms[d]));
        float ls = 4.f * tanhf(ms[DD + d]);
        float iv = __expf(-2.f * ls);
        g_W[((size_t)b * KK2 + d)      * LL + l] = -0.5f * iv;
        g_W[((size_t)b * KK2 + DD + d) * LL + l] = mu * iv;
        qmu += mu * mu * iv;
        sl  += ls;
    }
#pragma unroll
    for (int o = 16; o; o >>= 1) {
        qmu += __shfl_xor_sync(0xffffffffu, qmu, o);
        sl  += __shfl_xor_sync(0xffffffffu, sl, o);
    }
    if (lane == 0)
        g_C[b * LL + l] = -0.5f * qmu - 0.5f * sl - (float)DD * HALF_LOG2PI;
}

// ---------------------------------------------------------------------------
// K1: log_prob as batched SGEMM: lp[b,t,l] = sum_k X[t,k]*W[k,l] + C[l]
// ---------------------------------------------------------------------------
#define BK 16
__global__ void __launch_bounds__(256) lp_gemm(const float* __restrict__ mel,
                                               float* __restrict__ lp_out) {
    __shared__ float As[64][BK + 1];
    __shared__ float Bs[BK][64];

    int b  = blockIdx.z;
    int m0 = blockIdx.x * 64;
    int n0 = blockIdx.y * 64;
    int tid = threadIdx.x;
    int tx = tid & 15, ty = tid >> 4;

    const float* melb = mel + (size_t)b * TT * DD;
    const float* Wb   = g_W + (size_t)b * KK2 * LL;

    float acc[4][4];
#pragma unroll
    for (int i = 0; i < 4; i++)
#pragma unroll
        for (int j = 0; j < 4; j++) acc[i][j] = 0.f;

    for (int k0 = 0; k0 < KK2; k0 += BK) {
        bool sq = (k0 < DD);
        int  kc = sq ? k0 : (k0 - DD);
#pragma unroll
        for (int i = 0; i < 4; i++) {
            int lin = tid + i * 256;
            int mm = lin >> 4, kk = lin & 15;
            int t = m0 + mm; if (t > TT - 1) t = TT - 1;
            float v = melb[(size_t)t * DD + kc + kk];
            As[mm][kk] = sq ? v * v : v;
        }
#pragma unroll
        for (int i = 0; i < 4; i++) {
            int lin = tid + i * 256;
            int kk = lin >> 6, nn = lin & 63;
            int l = n0 + nn;
            Bs[kk][nn] = (l < LL) ? Wb[(size_t)(k0 + kk) * LL + l] : 0.f;
        }
        __syncthreads();
#pragma unroll
        for (int kk = 0; kk < BK; kk++) {
            float a0 = As[ty * 4 + 0][kk];
            float a1 = As[ty * 4 + 1][kk];
            float a2 = As[ty * 4 + 2][kk];
            float a3 = As[ty * 4 + 3][kk];
            float4 bv = *(const float4*)&Bs[kk][tx * 4];
            acc[0][0] += a0 * bv.x; acc[0][1] += a0 * bv.y; acc[0][2] += a0 * bv.z; acc[0][3] += a0 * bv.w;
            acc[1][0] += a1 * bv.x; acc[1][1] += a1 * bv.y; acc[1][2] += a1 * bv.z; acc[1][3] += a1 * bv.w;
            acc[2][0] += a2 * bv.x; acc[2][1] += a2 * bv.y; acc[2][2] += a2 * bv.z; acc[2][3] += a2 * bv.w;
            acc[3][0] += a3 * bv.x; acc[3][1] += a3 * bv.y; acc[3][2] += a3 * bv.z; acc[3][3] += a3 * bv.w;
        }
        __syncthreads();
    }

#pragma unroll
    for (int i = 0; i < 4; i++) {
        int t = m0 + ty * 4 + i;
        if (t >= TT) continue;
#pragma unroll
        for (int j = 0; j < 4; j++) {
            int l = n0 + tx * 4 + j;
            if (l < LL)
                lp_out[((size_t)b * TT + t) * LL + l] = acc[i][j] + g_C[b * LL + l];
        }
    }
}

// ---------------------------------------------------------------------------
// K2: single-warp-per-batch scan, register-resident alphas, zero inter-warp
// communication. Lane owns l = lane + 32k, k=0..4. Neighbor alpha[l-1] via
// one rotate-shuffle per chunk; lane 0 of chunk k takes the rotated value of
// chunk k-1 (which is lane 31's chunk k-1). 5 independent logaddexp chains
// per step give ILP; log2 domain to shorten the chain.
// ---------------------------------------------------------------------------
__device__ __forceinline__ float ex2f_(float x) {
    float r; asm("ex2.approx.ftz.f32 %0, %1;" : "=f"(r) : "f"(x)); return r;
}
__device__ __forceinline__ float lg2f_(float x) {
    float r; asm("lg2.approx.ftz.f32 %0, %1;" : "=f"(r) : "f"(x)); return r;
}

__global__ void __launch_bounds__(32) scan_kernel(const float* __restrict__ lp,
                                                  float* __restrict__ alphas,
                                                  const int* __restrict__ ml,
                                                  const int* __restrict__ cl,
                                                  float* __restrict__ loss) {
    int b    = blockIdx.x;
    int lane = threadIdx.x;
    int src  = (lane + 31) & 31;          // rotate-by-1 source lane

    const float* lpb = lp + (size_t)b * TT * LL;
    float* ab = alphas + (size_t)b * TT * LL;
    int mlb = ml[b] - 1;
    int clb = cl[b] - 1;
    int loss_k = ((clb & 31) == lane) ? (clb >> 5) : -1;

    float alpha[5];
#pragma unroll
    for (int k = 0; k < 5; k++) alpha[k] = NEG_INF2;
    if (lane == 0) alpha[0] = lpb[0] * LOG2E_F;

    // row 0 out
#pragma unroll
    for (int k = 0; k < 5; k++)
        ab[lane + 32 * k] = alpha[k] * LN2_F;

    // depth-4 lp prefetch (rows t+0..t+3 ahead of consumption)
    float pf0[5], pf1[5], pf2[5], pf3[5];
#pragma unroll
    for (int k = 0; k < 5; k++) {
        pf0[k] = lpb[(size_t)1 * LL + lane + 32 * k];
        pf1[k] = lpb[(size_t)2 * LL + lane + 32 * k];
        pf2[k] = lpb[(size_t)3 * LL + lane + 32 * k];
        pf3[k] = lpb[(size_t)4 * LL + lane + 32 * k];
    }

#pragma unroll 4
    for (int t = 1; t < TT; t++) {
        float lpv[5];
#pragma unroll
        for (int k = 0; k < 5; k++) { lpv[k] = pf0[k]; pf0[k] = pf1[k]; pf1[k] = pf2[k]; pf2[k] = pf3[k]; }
        int tl = (t + 4 < TT) ? (t + 4) : (TT - 1);
#pragma unroll
        for (int k = 0; k < 5; k++) pf3[k] = lpb[(size_t)tl * LL + lane + 32 * k];

        float rot[5];
#pragma unroll
        for (int k = 0; k < 5; k++)
            rot[k] = __shfl_sync(0xffffffffu, alpha[k], src);

        float prev[5];
        prev[0] = lane ? rot[0] : NEG_INF2;
#pragma unroll
        for (int k = 1; k < 5; k++)
            prev[k] = lane ? rot[k] : rot[k - 1];

#pragma unroll
        for (int k = 0; k < 5; k++) {
            float m = fmaxf(alpha[k], prev[k]);
            float d = fminf(alpha[k], prev[k]) - m;       // <= 0
            float s = lg2f_(1.f + ex2f_(d));
            alpha[k] = fmaf(lpv[k], LOG2E_F, m) + s;
        }

#pragma unroll
        for (int k = 0; k < 5; k++)
            ab[(size_t)t * LL + lane + 32 * k] = alpha[k] * LN2_F;

        if (t == mlb && loss_k >= 0)
            atomicAdd(loss, -alpha[loss_k] * (LN2_F / (float)BB));
    }
}

// ---------------------------------------------------------------------------
extern "C" void kernel_launch(void* const* d_in, const int* in_sizes, int n_in,
                              void* d_out, int out_size) {
    const float* mel      = (const float*)d_in[0];
    const float* mu_sigma = (const float*)d_in[1];
    const int*   ml       = (const int*)d_in[2];
    const int*   cl       = (const int*)d_in[3];

    float* out    = (float*)d_out;
    float* lp     = out;                              // [B,T,L]
    float* loss   = out + (size_t)BB * TT * LL;       // [1]
    float* alphas = loss + 1;                         // [B,T,L]

    param_kernel<<<(BB * LL * 32 + 127) / 128, 128>>>(mu_sigma, loss);

    dim3 g((TT + 63) / 64, (LL + 63) / 64, BB);       // 13 x 3 x 16
    lp_gemm<<<g, 256>>>(mel, lp);

    scan_kernel<<<BB, 32>>>(lp, alphas, ml, cl, loss);
}